// round 10
// baseline (speedup 1.0000x reference)
#include <cuda_runtime.h>
#include <cuda_fp16.h>
#include <math.h>
#include <stdint.h>

#define VV 32000
#define HH 256
#define BB 32
#define TT 128
#define VH (VV + HH)
#define MM (TT * BB)   // 4096 output rows
#define CR 4           // recurrence: CTAs per cluster
#define DPC 64         // hidden dims per CTA

// Scratch: hidden states and Wo, both rounded to fp16 for the output GEMM
__device__ __align__(256) __half g_Hall_h[(size_t)MM * HH];
__device__ __align__(256) __half g_Wo_h[(size_t)VV * HH];

__device__ __forceinline__ void st_cluster_f32(float* p, int rank, float v) {
    unsigned a = (unsigned)__cvta_generic_to_shared(p);
    unsigned r;
    asm volatile("mapa.shared::cluster.u32 %0, %1, %2;" : "=r"(r) : "r"(a), "r"(rank));
    asm volatile("st.shared::cluster.f32 [%0], %1;" :: "r"(r), "f"(v) : "memory");
}

__device__ __forceinline__ void cluster_sync_all() {
    asm volatile("barrier.cluster.arrive.aligned;" ::: "memory");
    asm volatile("barrier.cluster.wait.aligned;" ::: "memory");
}

__device__ __forceinline__ void cp16(unsigned smem_dst, const void* gsrc) {
    asm volatile("cp.async.cg.shared.global [%0], [%1], 16;"
                 :: "r"(smem_dst), "l"(gsrc) : "memory");
}

__device__ __forceinline__ void ldsm4(unsigned& r0, unsigned& r1,
                                      unsigned& r2, unsigned& r3, unsigned addr) {
    asm volatile("ldmatrix.sync.aligned.m8n8.x4.shared.b16 {%0,%1,%2,%3}, [%4];"
                 : "=r"(r0), "=r"(r1), "=r"(r2), "=r"(r3) : "r"(addr));
}

// ---------------------------------------------------------------------------
// Kernel 0: round Wo to fp16 once (8.192M elements).
// ---------------------------------------------------------------------------
__global__ __launch_bounds__(256) void cvt_wo(const float* __restrict__ Wo) {
    size_t i = ((size_t)blockIdx.x * 256 + threadIdx.x) * 4;
    float4 v = *(const float4*)(Wo + i);
    __half2 h01 = __floats2half2_rn(v.x, v.y);
    __half2 h23 = __floats2half2_rn(v.z, v.w);
    uint2 o;
    o.x = *(const unsigned*)&h01;
    o.y = *(const unsigned*)&h23;
    *(uint2*)(g_Wo_h + i) = o;
}

// ---------------------------------------------------------------------------
// Kernel 1: GRU recurrence (unchanged from round 9 — known good ~355us).
// ---------------------------------------------------------------------------
#define W_FLOATS 49152
#define SM_FLOATS (W_FLOATS + 256 + 256 + 192 + 1024 + 128)
#define SMEM_BYTES (SM_FLOATS * 4)

__global__ void __cluster_dims__(CR, 1, 1) __launch_bounds__(256, 1) rnn_recur(
    const int* __restrict__ X, const float* __restrict__ H0,
    const float* __restrict__ Wz, const float* __restrict__ bz,
    const float* __restrict__ Wr, const float* __restrict__ br,
    const float* __restrict__ Wh, const float* __restrict__ bh,
    float* __restrict__ hf_out, int write_hf)
{
    extern __shared__ float smf[];
    float* wT   = smf;
    float* sH   = wT + W_FLOATS;
    float* sRH  = sH + 256;
    float* sG   = sRH + 256;
    float* part = sG + 192;
    int*   sX   = (int*)(part + 1024);

    const int tid   = threadIdx.x;
    const int b     = blockIdx.x / CR;
    const int crank = blockIdx.x % CR;
    const int dim0  = DPC * crank;

    {
        for (int fid = tid; fid < 3 * 64 * 64; fid += 256) {
            int g = fid >> 12;
            int rem = fid & 4095;
            int j = rem >> 6;
            int k4 = rem & 63;
            const float* W = (g == 0) ? Wz : (g == 1) ? Wr : Wh;
            float4 v = *(const float4*)(W + (size_t)(dim0 + j) * VH + VV + k4 * 4);
            float* wg = wT + g * 16384;
            int k = k4 * 4;
            wg[(k    ) * 64 + (j ^ (((k    ) & 7) << 3))] = v.x;
            wg[(k + 1) * 64 + (j ^ (((k + 1) & 7) << 3))] = v.y;
            wg[(k + 2) * 64 + (j ^ (((k + 2) & 7) << 3))] = v.z;
            wg[(k + 3) * 64 + (j ^ (((k + 3) & 7) << 3))] = v.w;
        }
        if (tid < 128) sX[tid] = X[b * TT + tid];
        sH[tid] = H0[b * HH + tid];
    }

    float bias_a = 0.f, bias_h = 0.f;
    if (tid < 128) {
        int g = tid >> 6, j = tid & 63;
        bias_a = (g ? br : bz)[dim0 + j];
    }
    if (tid < 64) bias_h = bh[dim0 + tid];

    __syncthreads();

    float zreg = 0.f;
    float lasth = 0.f;

    for (int t = 0; t < TT; t++) {
        const int x = sX[t];
        if (tid < 192) {
            int g = tid >> 6, j = tid & 63;
            const float* W = (g == 0) ? Wz : (g == 1) ? Wr : Wh;
            sG[tid] = __ldg(W + (size_t)(dim0 + j) * VH + x);
        }

        {   // phase A: z and r matvecs over sH
            int g = tid >> 7;
            int s = (tid >> 4) & 7;
            int j4 = (tid & 15) << 2;
            const float* wg = wT + g * 16384 + s * 32 * 64;
            float a0 = 0.f, a1 = 0.f, a2 = 0.f, a3 = 0.f;
            #pragma unroll
            for (int kk = 0; kk < 32; kk++) {
                const float4 w = *(const float4*)(wg + kk * 64 + (j4 ^ ((kk & 7) << 3)));
                float hk = sH[s * 32 + kk];
                a0 += w.x * hk; a1 += w.y * hk; a2 += w.z * hk; a3 += w.w * hk;
            }
            *(float4*)(part + (g * 8 + s) * 64 + j4) = make_float4(a0, a1, a2, a3);
        }
        __syncthreads();

        if (tid < 128) {
            int g = tid >> 6, j = tid & 63;
            float a = bias_a + sG[g * 64 + j];
            #pragma unroll
            for (int s = 0; s < 8; s++) a += part[(g * 8 + s) * 64 + j];
            float sig = 1.f / (1.f + __expf(-a));
            if (g == 0) {
                zreg = sig;
            } else {
                float rh = sig * sH[dim0 + j];
                #pragma unroll
                for (int rk = 0; rk < CR; rk++) st_cluster_f32(&sRH[dim0 + j], rk, rh);
            }
        }
        cluster_sync_all();

        {   // phase B: h-candidate matvec over sRH
            int s2 = tid >> 4;
            int j4 = (tid & 15) << 2;
            const float* wg = wT + 2 * 16384 + s2 * 16 * 64;
            float a0 = 0.f, a1 = 0.f, a2 = 0.f, a3 = 0.f;
            #pragma unroll
            for (int kk = 0; kk < 16; kk++) {
                const float4 w = *(const float4*)(wg + kk * 64 + (j4 ^ ((kk & 7) << 3)));
                float hk = sRH[s2 * 16 + kk];
                a0 += w.x * hk; a1 += w.y * hk; a2 += w.z * hk; a3 += w.w * hk;
            }
            *(float4*)(part + s2 * 64 + j4) = make_float4(a0, a1, a2, a3);
        }
        __syncthreads();

        if (tid < 64) {
            int j = tid;
            float a = bias_h + sG[128 + j];
            #pragma unroll
            for (int s = 0; s < 16; s++) a += part[s * 64 + j];
            float e = __expf(2.f * a);
            float hv = (e - 1.f) / (e + 1.f);
            float hp = sH[dim0 + j];
            float hn = zreg * hv + (1.f - zreg) * hp;
            g_Hall_h[((size_t)t * BB + b) * HH + dim0 + j] = __float2half_rn(hn);
            #pragma unroll
            for (int rk = 0; rk < CR; rk++) st_cluster_f32(&sH[dim0 + j], rk, hn);
            lasth = hn;
        }
        cluster_sync_all();
    }

    if (write_hf && tid < 64)
        hf_out[b * HH + dim0 + tid] = lasth;
}

// ---------------------------------------------------------------------------
// Kernel 2: output projection, fp16 mma.sync.m16n8k16 (f32 accumulate).
// CTA 128x128, 4 warps, warp tile 64x64, BK=64, 2-stage cp.async.
// NEW: ldmatrix.m8n8.x4 fragment feeds — 8 LDSM per k-step per warp instead
// of 32 scalar LDS. PKH=72 (144B rows): rows land 16B apart in bank space ->
// each 8-row LDSM phase tiles the 128B crossbar conflict-free.
// ---------------------------------------------------------------------------
#define BM 128
#define BN 128
#define BKH 64
#define PKH 72
#define TILEH (BM * PKH)                  // 9216 halves = 18432 B per matrix
#define STAGEH (2 * TILEH)                // A+B per stage
#define GEMM_SMEM_BYTES (2 * STAGEH * 2)  // 73728 B
#define NCHUNK (HH / BKH)                 // 4

__global__ __launch_bounds__(128, 2) void out_gemm(
    const float* __restrict__ bo, float* __restrict__ Y)
{
    extern __shared__ __half smh[];
    const int m0 = blockIdx.y * BM;
    const int n0 = blockIdx.x * BN;
    const int tid = threadIdx.x;
    const int warp = tid >> 5, lane = tid & 31;
    const int wm = warp >> 1, wn = warp & 1;
    const int g = lane >> 2, tg = lane & 3;

    const int lrow = tid >> 3;   // 0..15
    const int lc8  = tid & 7;    // 16B column group (8 halves)

    // ldmatrix lane addressing: row select + k-half select
    const int lsel = lane & 15;          // row within 16-row fragment
    const int lk   = (lane >> 4) * 8;    // +8 halves for upper two tiles

    const unsigned smem_base = (unsigned)__cvta_generic_to_shared(smh);

    float c[4][8][4];
    #pragma unroll
    for (int a = 0; a < 4; a++)
        #pragma unroll
        for (int q = 0; q < 8; q++)
            #pragma unroll
            for (int d = 0; d < 4; d++) c[a][q][d] = 0.f;

    auto issue = [&](int stage, int kc) {
        unsigned sa = smem_base + (unsigned)(stage * STAGEH) * 2u;
        unsigned sb = sa + (unsigned)TILEH * 2u;
        #pragma unroll
        for (int j = 0; j < 8; j++) {
            int m = lrow + j * 16;
            unsigned off = (unsigned)(m * PKH + lc8 * 8) * 2u;
            cp16(sa + off, g_Hall_h + (size_t)(m0 + m) * HH + kc * BKH + lc8 * 8);
            cp16(sb + off, g_Wo_h   + (size_t)(n0 + m) * HH + kc * BKH + lc8 * 8);
        }
        asm volatile("cp.async.commit_group;" ::: "memory");
    };

    issue(0, 0);

    for (int kc = 0; kc < NCHUNK; kc++) {
        if (kc + 1 < NCHUNK) {
            issue((kc + 1) & 1, kc + 1);
            asm volatile("cp.async.wait_group 1;" ::: "memory");
        } else {
            asm volatile("cp.async.wait_group 0;" ::: "memory");
        }
        __syncthreads();

        // stage bases (half-indexed addresses, *2 for bytes)
        unsigned sa = smem_base + (unsigned)((kc & 1) * STAGEH) * 2u;
        unsigned sb = sa + (unsigned)TILEH * 2u;

        #pragma unroll
        for (int kk = 0; kk < BKH; kk += 16) {
            unsigned afr[4][4], bfr[4][4];
            #pragma unroll
            for (int mt = 0; mt < 4; mt++) {
                int rb = wm * 64 + mt * 16;
                unsigned addr = sa + (unsigned)((rb + lsel) * PKH + kk + lk) * 2u;
                ldsm4(afr[mt][0], afr[mt][1], afr[mt][2], afr[mt][3], addr);
            }
            #pragma unroll
            for (int p = 0; p < 4; p++) {      // nt pair p -> nt=2p, 2p+1
                int cb = wn * 64 + p * 16;
                unsigned addr = sb + (unsigned)((cb + lsel) * PKH + kk + lk) * 2u;
                ldsm4(bfr[p][0], bfr[p][1], bfr[p][2], bfr[p][3], addr);
            }
            #pragma unroll
            for (int p = 0; p < 4; p++) {
                #pragma unroll
                for (int h = 0; h < 2; h++) {  // nt = 2p + h
                    int nt = 2 * p + h;
                    unsigned b0 = bfr[p][h];       // k 0-7 of this nt
                    unsigned b1 = bfr[p][h + 2];   // k 8-15 of this nt
                    #pragma unroll
                    for (int mt = 0; mt < 4; mt++) {
                        asm volatile(
                            "mma.sync.aligned.m16n8k16.row.col.f32.f16.f16.f32 "
                            "{%0,%1,%2,%3}, {%4,%5,%6,%7}, {%8,%9}, {%0,%1,%2,%3};\n"
                            : "+f"(c[mt][nt][0]), "+f"(c[mt][nt][1]),
                              "+f"(c[mt][nt][2]), "+f"(c[mt][nt][3])
                            : "r"(afr[mt][0]), "r"(afr[mt][1]),
                              "r"(afr[mt][2]), "r"(afr[mt][3]),
                              "r"(b0), "r"(b1));
                    }
                }
            }
        }
        __syncthreads();
    }

    // epilogue: add bias, float2 stores
    #pragma unroll
    for (int nt = 0; nt < 8; nt++) {
        int cc = n0 + wn * 64 + nt * 8 + tg * 2;
        float bo0 = __ldg(bo + cc), bo1 = __ldg(bo + cc + 1);
        #pragma unroll
        for (int mt = 0; mt < 4; mt++) {
            int rr = m0 + wm * 64 + mt * 16 + g;
            float2 v0 = make_float2(c[mt][nt][0] + bo0, c[mt][nt][1] + bo1);
            float2 v1 = make_float2(c[mt][nt][2] + bo0, c[mt][nt][3] + bo1);
            *(float2*)(Y + (size_t)rr * VV + cc)       = v0;
            *(float2*)(Y + (size_t)(rr + 8) * VV + cc) = v1;
        }
    }
}

// ---------------------------------------------------------------------------
extern "C" void kernel_launch(void* const* d_in, const int* in_sizes, int n_in,
                              void* d_out, int out_size) {
    const int*   X  = (const int*)  d_in[0];
    const float* H0 = (const float*)d_in[1];
    const float* Wz = (const float*)d_in[2];
    const float* bz = (const float*)d_in[3];
    const float* Wr = (const float*)d_in[4];
    const float* br = (const float*)d_in[5];
    const float* Wh = (const float*)d_in[6];
    const float* bh = (const float*)d_in[7];
    const float* Wo = (const float*)d_in[8];
    const float* bo = (const float*)d_in[9];
    float* Y = (float*)d_out;

    const long long ys_elems = (long long)MM * VV;
    int write_hf = ((long long)out_size > ys_elems) ? 1 : 0;

    cudaFuncSetAttribute(rnn_recur, cudaFuncAttributeMaxDynamicSharedMemorySize,
                         SMEM_BYTES);
    cudaFuncSetAttribute(out_gemm, cudaFuncAttributeMaxDynamicSharedMemorySize,
                         GEMM_SMEM_BYTES);

    cvt_wo<<<(VV * HH) / (256 * 4), 256>>>(Wo);

    rnn_recur<<<BB * CR, 256, SMEM_BYTES>>>(X, H0, Wz, bz, Wr, br, Wh, bh,
                                            Y + ys_elems, write_hf);

    dim3 grid(VV / BN, MM / BM);   // 250 x 32
    out_gemm<<<grid, 128, GEMM_SMEM_BYTES>>>(bo, Y);
}

// round 11
// speedup vs baseline: 1.1318x; 1.1318x over previous
#include <cuda_runtime.h>
#include <cuda_fp16.h>
#include <math.h>
#include <stdint.h>

#define VV 32000
#define HH 256
#define BB 32
#define TT 128
#define VH (VV + HH)
#define MM (TT * BB)   // 4096 output rows
#define CR 4           // recurrence: CTAs per cluster
#define DPC 64         // hidden dims per CTA

// Scratch: hidden states and Wo, both rounded to fp16 for the output GEMM
__device__ __align__(256) __half g_Hall_h[(size_t)MM * HH];
__device__ __align__(256) __half g_Wo_h[(size_t)VV * HH];

__device__ __forceinline__ void st_cluster_f32(float* p, int rank, float v) {
    unsigned a = (unsigned)__cvta_generic_to_shared(p);
    unsigned r;
    asm volatile("mapa.shared::cluster.u32 %0, %1, %2;" : "=r"(r) : "r"(a), "r"(rank));
    asm volatile("st.shared::cluster.f32 [%0], %1;" :: "r"(r), "f"(v) : "memory");
}

__device__ __forceinline__ void cluster_sync_all() {
    asm volatile("barrier.cluster.arrive.aligned;" ::: "memory");
    asm volatile("barrier.cluster.wait.aligned;" ::: "memory");
}

__device__ __forceinline__ void cp16(unsigned smem_dst, const void* gsrc) {
    asm volatile("cp.async.cg.shared.global [%0], [%1], 16;"
                 :: "r"(smem_dst), "l"(gsrc) : "memory");
}

// ---------------------------------------------------------------------------
// Kernel 0: round Wo to fp16 once (8.192M elements).
// ---------------------------------------------------------------------------
__global__ __launch_bounds__(256) void cvt_wo(const float* __restrict__ Wo) {
    size_t i = ((size_t)blockIdx.x * 256 + threadIdx.x) * 4;
    float4 v = *(const float4*)(Wo + i);
    __half2 h01 = __floats2half2_rn(v.x, v.y);
    __half2 h23 = __floats2half2_rn(v.z, v.w);
    uint2 o;
    o.x = *(const unsigned*)&h01;
    o.y = *(const unsigned*)&h23;
    *(uint2*)(g_Wo_h + i) = o;
}

// ---------------------------------------------------------------------------
// Kernel 1: GRU recurrence. NEW this round:
//  (a) embedding gathers prefetched one step ahead (LDG latency hidden by
//      previous step's compute; sG written from registers)
//  (b) h / rh broadcast operands preloaded to registers before matvec loops
// Both preserve arithmetic order exactly.
// ---------------------------------------------------------------------------
#define W_FLOATS 49152
#define SM_FLOATS (W_FLOATS + 256 + 256 + 192 + 1024 + 128)
#define SMEM_BYTES (SM_FLOATS * 4)

__global__ void __cluster_dims__(CR, 1, 1) __launch_bounds__(256, 1) rnn_recur(
    const int* __restrict__ X, const float* __restrict__ H0,
    const float* __restrict__ Wz, const float* __restrict__ bz,
    const float* __restrict__ Wr, const float* __restrict__ br,
    const float* __restrict__ Wh, const float* __restrict__ bh,
    float* __restrict__ hf_out, int write_hf)
{
    extern __shared__ float smf[];
    float* wT   = smf;
    float* sH   = wT + W_FLOATS;
    float* sRH  = sH + 256;
    float* sG   = sRH + 256;
    float* part = sG + 192;
    int*   sX   = (int*)(part + 1024);

    const int tid   = threadIdx.x;
    const int b     = blockIdx.x / CR;
    const int crank = blockIdx.x % CR;
    const int dim0  = DPC * crank;

    {
        for (int fid = tid; fid < 3 * 64 * 64; fid += 256) {
            int g = fid >> 12;
            int rem = fid & 4095;
            int j = rem >> 6;
            int k4 = rem & 63;
            const float* W = (g == 0) ? Wz : (g == 1) ? Wr : Wh;
            float4 v = *(const float4*)(W + (size_t)(dim0 + j) * VH + VV + k4 * 4);
            float* wg = wT + g * 16384;
            int k = k4 * 4;
            wg[(k    ) * 64 + (j ^ (((k    ) & 7) << 3))] = v.x;
            wg[(k + 1) * 64 + (j ^ (((k + 1) & 7) << 3))] = v.y;
            wg[(k + 2) * 64 + (j ^ (((k + 2) & 7) << 3))] = v.z;
            wg[(k + 3) * 64 + (j ^ (((k + 3) & 7) << 3))] = v.w;
        }
        if (tid < 128) sX[tid] = X[b * TT + tid];
        sH[tid] = H0[b * HH + tid];
    }

    float bias_a = 0.f, bias_h = 0.f;
    if (tid < 128) {
        int g = tid >> 6, j = tid & 63;
        bias_a = (g ? br : bz)[dim0 + j];
    }
    if (tid < 64) bias_h = bh[dim0 + tid];

    // per-thread gather row pointer (invariant across steps)
    const float* grow = nullptr;
    if (tid < 192) {
        int g = tid >> 6, j = tid & 63;
        const float* W = (g == 0) ? Wz : (g == 1) ? Wr : Wh;
        grow = W + (size_t)(dim0 + j) * VH;
    }

    __syncthreads();

    // prefetch step-0 gather
    float gpre = 0.f;
    if (tid < 192) gpre = __ldg(grow + sX[0]);

    float zreg = 0.f;
    float lasth = 0.f;

    for (int t = 0; t < TT; t++) {
        // publish this step's gathers (registers -> smem; no LDG stall here)
        if (tid < 192) sG[tid] = gpre;
        // prefetch next step's gathers; latency hidden by phases A+B below
        if (t + 1 < TT && tid < 192) gpre = __ldg(grow + sX[t + 1]);

        {   // phase A: z and r matvecs over sH
            int g = tid >> 7;
            int s = (tid >> 4) & 7;
            int j4 = (tid & 15) << 2;
            const float* wg = wT + g * 16384 + s * 32 * 64;
            // preload the 32 h values for this k-slice into registers
            float hreg[32];
            const float4* sH4 = (const float4*)(sH + s * 32);
            #pragma unroll
            for (int q = 0; q < 8; q++) {
                float4 h4 = sH4[q];
                hreg[q * 4 + 0] = h4.x; hreg[q * 4 + 1] = h4.y;
                hreg[q * 4 + 2] = h4.z; hreg[q * 4 + 3] = h4.w;
            }
            float a0 = 0.f, a1 = 0.f, a2 = 0.f, a3 = 0.f;
            #pragma unroll
            for (int kk = 0; kk < 32; kk++) {
                const float4 w = *(const float4*)(wg + kk * 64 + (j4 ^ ((kk & 7) << 3)));
                float hk = hreg[kk];
                a0 += w.x * hk; a1 += w.y * hk; a2 += w.z * hk; a3 += w.w * hk;
            }
            *(float4*)(part + (g * 8 + s) * 64 + j4) = make_float4(a0, a1, a2, a3);
        }
        __syncthreads();

        if (tid < 128) {
            int g = tid >> 6, j = tid & 63;
            float a = bias_a + sG[g * 64 + j];
            #pragma unroll
            for (int s = 0; s < 8; s++) a += part[(g * 8 + s) * 64 + j];
            float sig = 1.f / (1.f + __expf(-a));
            if (g == 0) {
                zreg = sig;
            } else {
                float rh = sig * sH[dim0 + j];
                #pragma unroll
                for (int rk = 0; rk < CR; rk++) st_cluster_f32(&sRH[dim0 + j], rk, rh);
            }
        }
        cluster_sync_all();

        {   // phase B: h-candidate matvec over sRH
            int s2 = tid >> 4;
            int j4 = (tid & 15) << 2;
            const float* wg = wT + 2 * 16384 + s2 * 16 * 64;
            float hreg[16];
            const float4* sRH4 = (const float4*)(sRH + s2 * 16);
            #pragma unroll
            for (int q = 0; q < 4; q++) {
                float4 h4 = sRH4[q];
                hreg[q * 4 + 0] = h4.x; hreg[q * 4 + 1] = h4.y;
                hreg[q * 4 + 2] = h4.z; hreg[q * 4 + 3] = h4.w;
            }
            float a0 = 0.f, a1 = 0.f, a2 = 0.f, a3 = 0.f;
            #pragma unroll
            for (int kk = 0; kk < 16; kk++) {
                const float4 w = *(const float4*)(wg + kk * 64 + (j4 ^ ((kk & 7) << 3)));
                float hk = hreg[kk];
                a0 += w.x * hk; a1 += w.y * hk; a2 += w.z * hk; a3 += w.w * hk;
            }
            *(float4*)(part + s2 * 64 + j4) = make_float4(a0, a1, a2, a3);
        }
        __syncthreads();

        if (tid < 64) {
            int j = tid;
            float a = bias_h + sG[128 + j];
            #pragma unroll
            for (int s = 0; s < 16; s++) a += part[s * 64 + j];
            float e = __expf(2.f * a);
            float hv = (e - 1.f) / (e + 1.f);
            float hp = sH[dim0 + j];
            float hn = zreg * hv + (1.f - zreg) * hp;
            g_Hall_h[((size_t)t * BB + b) * HH + dim0 + j] = __float2half_rn(hn);
            #pragma unroll
            for (int rk = 0; rk < CR; rk++) st_cluster_f32(&sH[dim0 + j], rk, hn);
            lasth = hn;
        }
        cluster_sync_all();
    }

    if (write_hf && tid < 64)
        hf_out[b * HH + dim0 + tid] = lasth;
}

// ---------------------------------------------------------------------------
// Kernel 2: output projection, fp16 mma.sync.m16n8k16 (f32 accumulate).
// Round-9 version (scalar-LDS fragment feed) — known good; ldmatrix variant
// regressed and was reverted.
// ---------------------------------------------------------------------------
#define BM 128
#define BN 128
#define BKH 64
#define PKH 72
#define TILEH (BM * PKH)                  // 9216 halves = 18432 B per matrix
#define STAGEH (2 * TILEH)                // A+B per stage
#define GEMM_SMEM_BYTES (2 * STAGEH * 2)  // 73728 B
#define NCHUNK (HH / BKH)                 // 4

__global__ __launch_bounds__(128, 2) void out_gemm(
    const float* __restrict__ bo, float* __restrict__ Y)
{
    extern __shared__ __half smh[];
    const int m0 = blockIdx.y * BM;
    const int n0 = blockIdx.x * BN;
    const int tid = threadIdx.x;
    const int warp = tid >> 5, lane = tid & 31;
    const int wm = warp >> 1, wn = warp & 1;
    const int g = lane >> 2, tg = lane & 3;

    const int lrow = tid >> 3;   // 0..15
    const int lc8  = tid & 7;    // 16B column group (8 halves)

    const unsigned smem_base = (unsigned)__cvta_generic_to_shared(smh);

    float c[4][8][4];
    #pragma unroll
    for (int a = 0; a < 4; a++)
        #pragma unroll
        for (int q = 0; q < 8; q++)
            #pragma unroll
            for (int d = 0; d < 4; d++) c[a][q][d] = 0.f;

    auto issue = [&](int stage, int kc) {
        unsigned sa = smem_base + (unsigned)(stage * STAGEH) * 2u;
        unsigned sb = sa + (unsigned)TILEH * 2u;
        #pragma unroll
        for (int j = 0; j < 8; j++) {
            int m = lrow + j * 16;
            unsigned off = (unsigned)(m * PKH + lc8 * 8) * 2u;
            cp16(sa + off, g_Hall_h + (size_t)(m0 + m) * HH + kc * BKH + lc8 * 8);
            cp16(sb + off, g_Wo_h   + (size_t)(n0 + m) * HH + kc * BKH + lc8 * 8);
        }
        asm volatile("cp.async.commit_group;" ::: "memory");
    };

    issue(0, 0);

    for (int kc = 0; kc < NCHUNK; kc++) {
        if (kc + 1 < NCHUNK) {
            issue((kc + 1) & 1, kc + 1);
            asm volatile("cp.async.wait_group 1;" ::: "memory");
        } else {
            asm volatile("cp.async.wait_group 0;" ::: "memory");
        }
        __syncthreads();

        const __half* As = smh + (kc & 1) * STAGEH;
        const __half* Bs = As + TILEH;

        #pragma unroll
        for (int kk = 0; kk < BKH; kk += 16) {
            unsigned afr[4][4];
            #pragma unroll
            for (int mt = 0; mt < 4; mt++) {
                int rb = wm * 64 + mt * 16;
                afr[mt][0] = *(const unsigned*)(As + (rb + g    ) * PKH + kk + 2 * tg    );
                afr[mt][1] = *(const unsigned*)(As + (rb + g + 8) * PKH + kk + 2 * tg    );
                afr[mt][2] = *(const unsigned*)(As + (rb + g    ) * PKH + kk + 2 * tg + 8);
                afr[mt][3] = *(const unsigned*)(As + (rb + g + 8) * PKH + kk + 2 * tg + 8);
            }
            #pragma unroll
            for (int nt = 0; nt < 8; nt++) {
                int cb = wn * 64 + nt * 8;
                unsigned b0 = *(const unsigned*)(Bs + (cb + g) * PKH + kk + 2 * tg    );
                unsigned b1 = *(const unsigned*)(Bs + (cb + g) * PKH + kk + 2 * tg + 8);
                #pragma unroll
                for (int mt = 0; mt < 4; mt++) {
                    asm volatile(
                        "mma.sync.aligned.m16n8k16.row.col.f32.f16.f16.f32 "
                        "{%0,%1,%2,%3}, {%4,%5,%6,%7}, {%8,%9}, {%0,%1,%2,%3};\n"
                        : "+f"(c[mt][nt][0]), "+f"(c[mt][nt][1]),
                          "+f"(c[mt][nt][2]), "+f"(c[mt][nt][3])
                        : "r"(afr[mt][0]), "r"(afr[mt][1]),
                          "r"(afr[mt][2]), "r"(afr[mt][3]),
                          "r"(b0), "r"(b1));
                }
            }
        }
        __syncthreads();
    }

    // epilogue: add bias, float2 stores
    #pragma unroll
    for (int nt = 0; nt < 8; nt++) {
        int cc = n0 + wn * 64 + nt * 8 + tg * 2;
        float bo0 = __ldg(bo + cc), bo1 = __ldg(bo + cc + 1);
        #pragma unroll
        for (int mt = 0; mt < 4; mt++) {
            int rr = m0 + wm * 64 + mt * 16 + g;
            float2 v0 = make_float2(c[mt][nt][0] + bo0, c[mt][nt][1] + bo1);
            float2 v1 = make_float2(c[mt][nt][2] + bo0, c[mt][nt][3] + bo1);
            *(float2*)(Y + (size_t)rr * VV + cc)       = v0;
            *(float2*)(Y + (size_t)(rr + 8) * VV + cc) = v1;
        }
    }
}

// ---------------------------------------------------------------------------
extern "C" void kernel_launch(void* const* d_in, const int* in_sizes, int n_in,
                              void* d_out, int out_size) {
    const int*   X  = (const int*)  d_in[0];
    const float* H0 = (const float*)d_in[1];
    const float* Wz = (const float*)d_in[2];
    const float* bz = (const float*)d_in[3];
    const float* Wr = (const float*)d_in[4];
    const float* br = (const float*)d_in[5];
    const float* Wh = (const float*)d_in[6];
    const float* bh = (const float*)d_in[7];
    const float* Wo = (const float*)d_in[8];
    const float* bo = (const float*)d_in[9];
    float* Y = (float*)d_out;

    const long long ys_elems = (long long)MM * VV;
    int write_hf = ((long long)out_size > ys_elems) ? 1 : 0;

    cudaFuncSetAttribute(rnn_recur, cudaFuncAttributeMaxDynamicSharedMemorySize,
                         SMEM_BYTES);
    cudaFuncSetAttribute(out_gemm, cudaFuncAttributeMaxDynamicSharedMemorySize,
                         GEMM_SMEM_BYTES);

    cvt_wo<<<(VV * HH) / (256 * 4), 256>>>(Wo);

    rnn_recur<<<BB * CR, 256, SMEM_BYTES>>>(X, H0, Wz, bz, Wr, br, Wh, bh,
                                            Y + ys_elems, write_hf);

    dim3 grid(VV / BN, MM / BM);   // 250 x 32
    out_gemm<<<grid, 128, GEMM_SMEM_BYTES>>>(bo, Y);
}